// round 3
// baseline (speedup 1.0000x reference)
#include <cuda_runtime.h>

// Triplane field sampling, GB300.
// Phase 1: transpose each scale's grids [3, 72, r, r] -> [3, r, r, 72] so one
//          texel's 72 channels are one contiguous 288B record (9 full sectors).
// Phase 2: gather. One thread per (point, plane, float4-chunk) = 54 threads/pt.
//          Each thread: 4 scales x 4 corners LDG.128, bilinear, cumulative sum
//          across scales held in registers, 4 coalesced float4 stores.

#define CDIM 72
#define NCHUNK 18            // 72 / 4
#define THREADS_PER_PT 54    // 3 planes * 18 chunks

// Scale table
__device__ __constant__ int d_dummy; // (unused; keeps nvcc happy if pruned)

static const int RES[4]  = {64, 128, 256, 512};
// float offsets into transposed scratch: 216 * cumulative r^2
static const int OFFS[4] = {0, 884736, 4423680, 18579456};
// total = 75,202,560 floats = 300.8 MB
__device__ float g_tp[75202560];

// ---------------- Phase 1: tiled transpose ----------------
// in:  [3, 72, r, r]   (c-major texels)
// out: g_tp + off : [3, r, r, 72]
// Tile 32(channels) x 32(x) for fixed (plane, y).
__global__ __launch_bounds__(256) void transpose_k(
    const float* __restrict__ in, int off, int r)
{
    __shared__ float tile[32][33];
    const int p  = blockIdx.z / r;
    const int y  = blockIdx.z - p * r;
    const int x0 = blockIdx.x * 32;
    const int c0 = blockIdx.y * 32;
    const int tx = threadIdx.x;      // 0..31
    const int ty = threadIdx.y;      // 0..7

    // load: rows = channels (strided r*r), cols = x (coalesced)
    #pragma unroll
    for (int i = 0; i < 4; i++) {
        int cc = c0 + ty + i * 8;
        float v = 0.0f;
        if (cc < CDIM) {
            v = in[((size_t)(p * CDIM + cc) * r + y) * r + (x0 + tx)];
        }
        tile[ty + i * 8][tx] = v;
    }
    __syncthreads();

    float* out = g_tp + off;
    // write: tx indexes channel (contiguous), rows = x
    #pragma unroll
    for (int i = 0; i < 4; i++) {
        int xx = x0 + ty + i * 8;
        int cc = c0 + tx;
        if (cc < CDIM) {
            out[((size_t)(p * r + y) * r + xx) * CDIM + cc] = tile[tx][ty + i * 8];
        }
    }
}

// ---------------- Phase 2: gather + bilinear + cumulative sum ----------------
__global__ __launch_bounds__(256) void gather_k(
    const float* __restrict__ pts, float* __restrict__ out, int N)
{
    const int gid = blockIdx.x * blockDim.x + threadIdx.x;
    if (gid >= N * THREADS_PER_PT) return;

    const int n = gid / THREADS_PER_PT;
    const int j = gid - n * THREADS_PER_PT;
    const int p = j / NCHUNK;            // plane 0..2
    const int k = j - p * NCHUNK;        // float4 chunk 0..17

    // pts_n = -pts / 1.6  (== (pts - b) * (2 / (-2b)) - 1 with b=1.6)
    const float d0 = -0.625f * __ldg(&pts[3 * n + 0]);
    const float d1 = -0.625f * __ldg(&pts[3 * n + 1]);
    const float d2 = -0.625f * __ldg(&pts[3 * n + 2]);

    // plane coordinate combos: p0 -> (d0, d1), p1 -> (d0, d2), p2 -> (d1, d2)
    const float cx = (p == 2) ? d1 : d0;
    const float cy = (p == 0) ? d1 : d2;

    const int   resos[4] = {64, 128, 256, 512};
    const int   offs[4]  = {0, 884736, 4423680, 18579456};

    float4 acc = make_float4(0.f, 0.f, 0.f, 0.f);
    float* outrow = out + (size_t)n * 864 + p * CDIM + k * 4;

    #pragma unroll
    for (int s = 0; s < 4; s++) {
        const int r = resos[s];
        const float rm1 = (float)(r - 1);

        float fx = (cx + 1.0f) * 0.5f * rm1;
        float fy = (cy + 1.0f) * 0.5f * rm1;
        fx = fminf(fmaxf(fx, 0.0f), rm1);
        fy = fminf(fmaxf(fy, 0.0f), rm1);

        const float x0f = floorf(fx);
        const float y0f = floorf(fy);
        const float wx = fx - x0f;
        const float wy = fy - y0f;
        const int x0 = (int)x0f;
        const int y0 = (int)y0f;
        const int x1 = min(x0 + 1, r - 1);
        const int y1 = min(y0 + 1, r - 1);

        const float* base = g_tp + offs[s];
        const size_t row0 = (size_t)(p * r + y0) * r;
        const size_t row1 = (size_t)(p * r + y1) * r;

        const float4 v00 = __ldg((const float4*)(base + (row0 + x0) * CDIM) + k);
        const float4 v01 = __ldg((const float4*)(base + (row0 + x1) * CDIM) + k);
        const float4 v10 = __ldg((const float4*)(base + (row1 + x0) * CDIM) + k);
        const float4 v11 = __ldg((const float4*)(base + (row1 + x1) * CDIM) + k);

        const float w00 = (1.0f - wx) * (1.0f - wy);
        const float w01 = wx * (1.0f - wy);
        const float w10 = (1.0f - wx) * wy;
        const float w11 = wx * wy;

        acc.x += v00.x * w00 + v01.x * w01 + v10.x * w10 + v11.x * w11;
        acc.y += v00.y * w00 + v01.y * w01 + v10.y * w10 + v11.y * w11;
        acc.z += v00.z * w00 + v01.z * w01 + v10.z * w10 + v11.z * w11;
        acc.w += v00.w * w00 + v01.w * w01 + v10.w * w10 + v11.w * w11;

        *(float4*)(outrow + s * 216) = acc;
    }
}

extern "C" void kernel_launch(void* const* d_in, const int* in_sizes, int n_in,
                              void* d_out, int out_size)
{
    const float* pts = (const float*)d_in[0];
    const int N = in_sizes[0] / 3;
    float* out = (float*)d_out;

    static const int res[4]  = {64, 128, 256, 512};
    static const int offs[4] = {0, 884736, 4423680, 18579456};

    // Phase 1: transpose each scale into the contiguous-channel scratch.
    for (int s = 0; s < 4; s++) {
        const float* g = (const float*)d_in[1 + s];
        const int r = res[s];
        dim3 grid(r / 32, 3, 3 * r);   // (x-tiles, c-tiles, plane*y)
        dim3 block(32, 8);
        transpose_k<<<grid, block>>>(g, offs[s], r);
    }

    // Phase 2: gather.
    const int total = N * THREADS_PER_PT;
    const int threads = 256;
    const int blocks = (total + threads - 1) / threads;
    gather_k<<<blocks, threads>>>(pts, out, N);
}

// round 5
// speedup vs baseline: 1.2268x; 1.2268x over previous
#include <cuda_runtime.h>

// Triplane sampling, GB300 (sm_103a).
// Pipeline per launch: [zero hist] -> [histogram by 3D Morton bucket] ->
// [block scan] -> [scatter: permuted pts] -> [4x transpose to channel-major
// scratch] -> [gather: bilinear x 4 scales, cumulative, streaming stores].

#define CDIM 72
#define NCHUNK 18            // 72 / 4 float4 chunks
#define THREADS_PER_PT 54    // 3 planes * 18 chunks
#define NBUCKET 4096

// transposed grids: [scale][plane][texel][72] floats; 216 * sum(r^2) = 75,202,560
__device__ float g_tp[75202560];
__device__ float g_ptss[262144 * 3];   // spatially sorted points
__device__ int   g_perm[262144];       // sorted position -> original index
__device__ int   g_hist[NBUCKET];
__device__ int   g_base[NBUCKET];

// ---------------- sort: bucket key (3D Morton, 4 bits/dim) ----------------
__device__ __forceinline__ int pt_key(const float* __restrict__ pts, int n) {
    int k = 0;
    #pragma unroll
    for (int d = 0; d < 3; d++) {
        float u = fminf(fmaxf(-0.625f * pts[3 * n + d], -1.f), 1.f) * 0.5f + 0.5f;
        int q = min(15, (int)(u * 16.0f));
        #pragma unroll
        for (int b = 0; b < 4; b++)
            k |= ((q >> b) & 1) << (3 * b + d);
    }
    return k;
}

__global__ void zero_k() {
    g_hist[blockIdx.x * blockDim.x + threadIdx.x] = 0;
}

__global__ void hist_k(const float* __restrict__ pts, int N) {
    int n = blockIdx.x * blockDim.x + threadIdx.x;
    if (n < N) atomicAdd(&g_hist[pt_key(pts, n)], 1);
}

__global__ __launch_bounds__(512) void scan_k() {
    __shared__ int sh[512];
    const int t = threadIdx.x;
    int v[8];
    int s = 0;
    #pragma unroll
    for (int i = 0; i < 8; i++) { v[i] = g_hist[t * 8 + i]; s += v[i]; }
    sh[t] = s;
    __syncthreads();
    for (int off = 1; off < 512; off <<= 1) {
        int x = (t >= off) ? sh[t - off] : 0;
        __syncthreads();
        sh[t] += x;
        __syncthreads();
    }
    int excl = sh[t] - s;
    #pragma unroll
    for (int i = 0; i < 8; i++) { g_base[t * 8 + i] = excl; excl += v[i]; }
}

__global__ void scatter_k(const float* __restrict__ pts, int N) {
    int n = blockIdx.x * blockDim.x + threadIdx.x;
    if (n >= N) return;
    int pos = atomicAdd(&g_base[pt_key(pts, n)], 1);
    g_perm[pos] = n;
    g_ptss[pos * 3 + 0] = pts[n * 3 + 0];
    g_ptss[pos * 3 + 1] = pts[n * 3 + 1];
    g_ptss[pos * 3 + 2] = pts[n * 3 + 2];
}

// ---------------- transpose: [3,72,r,r] -> [3, r*r, 72] ----------------
// One block = one plane x 32 texels x all 72 channels. 288 threads, no
// bounds checks, padded smem (stride 77 -> conflict-free column stores),
// fully coalesced float4 writes.
__global__ __launch_bounds__(288) void transpose_k(
    const float* __restrict__ in, int off, int r2)
{
    __shared__ float tile[32 * 77];
    const int p   = blockIdx.y;
    const int t0  = blockIdx.x * 32;
    const int tid = threadIdx.x;

    const float* src = in + (size_t)p * CDIM * r2 + t0;
    #pragma unroll
    for (int i = 0; i < 8; i++) {
        int idx = i * 288 + tid;          // 0..2303
        int c = idx >> 5;
        int x = idx & 31;
        tile[x * 77 + c] = src[(size_t)c * r2 + x];
    }
    __syncthreads();

    float4* dst = (float4*)(g_tp + off) + ((size_t)p * r2 + t0) * NCHUNK;
    #pragma unroll
    for (int i = 0; i < 2; i++) {
        int lin = i * 288 + tid;          // 0..575
        int x = lin / NCHUNK;
        int q = lin - x * NCHUNK;
        const float* tp = tile + x * 77 + 4 * q;
        dst[lin] = make_float4(tp[0], tp[1], tp[2], tp[3]);
    }
}

// ---------------- gather ----------------
__global__ __launch_bounds__(256) void gather_k(
    float* __restrict__ out, int N)
{
    const int gid = blockIdx.x * blockDim.x + threadIdx.x;
    if (gid >= N * THREADS_PER_PT) return;

    const int n = gid / THREADS_PER_PT;       // sorted position
    const int j = gid - n * THREADS_PER_PT;
    const int p = j / NCHUNK;                 // plane
    const int k = j - p * NCHUNK;             // float4 chunk

    const float d0 = -0.625f * g_ptss[3 * n + 0];
    const float d1 = -0.625f * g_ptss[3 * n + 1];
    const float d2 = -0.625f * g_ptss[3 * n + 2];

    const float cx = (p == 2) ? d1 : d0;
    const float cy = (p == 0) ? d1 : d2;

    const int resos[4] = {64, 128, 256, 512};
    const int offs[4]  = {0, 884736, 4423680, 18579456};

    const int orig = g_perm[n];
    float* outrow = out + (size_t)orig * 864 + p * CDIM + k * 4;

    float4 acc = make_float4(0.f, 0.f, 0.f, 0.f);

    #pragma unroll
    for (int s = 0; s < 4; s++) {
        const int r = resos[s];
        const float rm1 = (float)(r - 1);

        float fx = (cx + 1.0f) * 0.5f * rm1;
        float fy = (cy + 1.0f) * 0.5f * rm1;
        fx = fminf(fmaxf(fx, 0.0f), rm1);
        fy = fminf(fmaxf(fy, 0.0f), rm1);

        const float x0f = floorf(fx);
        const float y0f = floorf(fy);
        const float wx = fx - x0f;
        const float wy = fy - y0f;
        const int x0 = (int)x0f;
        const int y0 = (int)y0f;
        const int x1 = min(x0 + 1, r - 1);
        const int y1 = min(y0 + 1, r - 1);

        const float* base = g_tp + offs[s];
        const size_t row0 = (size_t)(p * r + y0) * r;
        const size_t row1 = (size_t)(p * r + y1) * r;

        const float4 v00 = __ldg((const float4*)(base + (row0 + x0) * CDIM) + k);
        const float4 v01 = __ldg((const float4*)(base + (row0 + x1) * CDIM) + k);
        const float4 v10 = __ldg((const float4*)(base + (row1 + x0) * CDIM) + k);
        const float4 v11 = __ldg((const float4*)(base + (row1 + x1) * CDIM) + k);

        const float w00 = (1.0f - wx) * (1.0f - wy);
        const float w01 = wx * (1.0f - wy);
        const float w10 = (1.0f - wx) * wy;
        const float w11 = wx * wy;

        acc.x += v00.x * w00 + v01.x * w01 + v10.x * w10 + v11.x * w11;
        acc.y += v00.y * w00 + v01.y * w01 + v10.y * w10 + v11.y * w11;
        acc.z += v00.z * w00 + v01.z * w01 + v10.z * w10 + v11.z * w11;
        acc.w += v00.w * w00 + v01.w * w01 + v10.w * w10 + v11.w * w11;

        __stcs((float4*)(outrow + s * 216), acc);
    }
}

extern "C" void kernel_launch(void* const* d_in, const int* in_sizes, int n_in,
                              void* d_out, int out_size)
{
    const float* pts = (const float*)d_in[0];
    const int N = in_sizes[0] / 3;
    float* out = (float*)d_out;

    static const int res[4]  = {64, 128, 256, 512};
    static const int offs[4] = {0, 884736, 4423680, 18579456};

    // sort pipeline
    zero_k<<<NBUCKET / 256, 256>>>();
    hist_k<<<(N + 255) / 256, 256>>>(pts, N);
    scan_k<<<1, 512>>>();
    scatter_k<<<(N + 255) / 256, 256>>>(pts, N);

    // transposes
    for (int s = 0; s < 4; s++) {
        const float* g = (const float*)d_in[1 + s];
        const int r2 = res[s] * res[s];
        dim3 grid(r2 / 32, 3);
        transpose_k<<<grid, 288>>>(g, offs[s], r2);
    }

    // gather
    const int total = N * THREADS_PER_PT;
    gather_k<<<(total + 255) / 256, 256>>>(out, N);
}

// round 6
// speedup vs baseline: 1.2664x; 1.0323x over previous
#include <cuda_runtime.h>

// Triplane sampling, GB300 (sm_103a).
// Stream A (capture stream): 4x transpose -> gather
// Stream B (forked):         hist -> scan(+re-zero) -> scatter
// join before gather.

#define CDIM 72
#define NCHUNK 18            // 72 / 4 float4 chunks
#define THREADS_PER_PT 54    // 3 planes * 18 chunks
#define NBUCKET 4096

// transposed grids: [scale][plane][texel][72] floats; 216 * sum(r^2)
__device__ float g_tp[75202560];
__device__ float g_ptss[262144 * 3];   // spatially sorted points
__device__ int   g_perm[262144];       // sorted position -> original index
__device__ int   g_hist[NBUCKET];      // zero-initialized; scan_k re-zeroes
__device__ int   g_base[NBUCKET];

// ---------------- sort: bucket key (3D Morton, 4 bits/dim) ----------------
__device__ __forceinline__ int pt_key(const float* __restrict__ pts, int n) {
    int k = 0;
    #pragma unroll
    for (int d = 0; d < 3; d++) {
        float u = fminf(fmaxf(-0.625f * pts[3 * n + d], -1.f), 1.f) * 0.5f + 0.5f;
        int q = min(15, (int)(u * 16.0f));
        #pragma unroll
        for (int b = 0; b < 4; b++)
            k |= ((q >> b) & 1) << (3 * b + d);
    }
    return k;
}

__global__ void hist_k(const float* __restrict__ pts, int N) {
    int n = blockIdx.x * blockDim.x + threadIdx.x;
    if (n < N) atomicAdd(&g_hist[pt_key(pts, n)], 1);
}

__global__ __launch_bounds__(512) void scan_k() {
    __shared__ int sh[512];
    const int t = threadIdx.x;
    int v[8];
    int s = 0;
    #pragma unroll
    for (int i = 0; i < 8; i++) { v[i] = g_hist[t * 8 + i]; s += v[i]; }
    // restore the zero-state for the next graph replay
    #pragma unroll
    for (int i = 0; i < 8; i++) g_hist[t * 8 + i] = 0;
    sh[t] = s;
    __syncthreads();
    for (int off = 1; off < 512; off <<= 1) {
        int x = (t >= off) ? sh[t - off] : 0;
        __syncthreads();
        sh[t] += x;
        __syncthreads();
    }
    int excl = sh[t] - s;
    #pragma unroll
    for (int i = 0; i < 8; i++) { g_base[t * 8 + i] = excl; excl += v[i]; }
}

__global__ void scatter_k(const float* __restrict__ pts, int N) {
    int n = blockIdx.x * blockDim.x + threadIdx.x;
    if (n >= N) return;
    int pos = atomicAdd(&g_base[pt_key(pts, n)], 1);
    g_perm[pos] = n;
    g_ptss[pos * 3 + 0] = pts[n * 3 + 0];
    g_ptss[pos * 3 + 1] = pts[n * 3 + 1];
    g_ptss[pos * 3 + 2] = pts[n * 3 + 2];
}

// ---------------- transpose: [3,72,r2] -> [3, r2, 72] ----------------
// One block = one plane x 64 texels x 72 channels. 288 threads.
// Load: LDG.128 over texels (16 threads = 256B contiguous per channel row).
// smem stride 77: STS scalar (2-way conflicts), LDS scalar contiguous.
// Store: STG.128, block-contiguous.
__global__ __launch_bounds__(288) void transpose_k(
    const float* __restrict__ in, int off, int r2)
{
    __shared__ float tile[64 * 77];
    const int p   = blockIdx.y;
    const int t0  = blockIdx.x * 64;
    const int tid = threadIdx.x;

    const float* src = in + (size_t)p * CDIM * r2 + t0;
    #pragma unroll
    for (int i = 0; i < 4; i++) {
        int idx = i * 288 + tid;          // 0..1151
        int c = idx >> 4;                 // channel 0..71
        int v = idx & 15;                 // float4 index over 64 texels
        float4 d = __ldg((const float4*)(src + (size_t)c * r2) + v);
        float* tp = tile + (4 * v) * 77 + c;
        tp[0 * 77] = d.x;
        tp[1 * 77] = d.y;
        tp[2 * 77] = d.z;
        tp[3 * 77] = d.w;
    }
    __syncthreads();

    float4* dst = (float4*)(g_tp + off) + ((size_t)p * r2 + t0) * NCHUNK;
    #pragma unroll
    for (int i = 0; i < 4; i++) {
        int lin = i * 288 + tid;          // 0..1151
        int x = lin / NCHUNK;
        int q = lin - x * NCHUNK;
        const float* tp = tile + x * 77 + 4 * q;
        dst[lin] = make_float4(tp[0], tp[1], tp[2], tp[3]);
    }
}

// ---------------- gather ----------------
__global__ __launch_bounds__(256) void gather_k(
    float* __restrict__ out, int N)
{
    const int gid = blockIdx.x * blockDim.x + threadIdx.x;
    if (gid >= N * THREADS_PER_PT) return;

    const int n = gid / THREADS_PER_PT;       // sorted position
    const int j = gid - n * THREADS_PER_PT;
    const int p = j / NCHUNK;                 // plane
    const int k = j - p * NCHUNK;             // float4 chunk

    const float d0 = -0.625f * g_ptss[3 * n + 0];
    const float d1 = -0.625f * g_ptss[3 * n + 1];
    const float d2 = -0.625f * g_ptss[3 * n + 2];

    const float cx = (p == 2) ? d1 : d0;
    const float cy = (p == 0) ? d1 : d2;

    const int resos[4] = {64, 128, 256, 512};
    const int offs[4]  = {0, 884736, 4423680, 18579456};

    const int orig = g_perm[n];
    float* outrow = out + (size_t)orig * 864 + p * CDIM + k * 4;

    float4 acc = make_float4(0.f, 0.f, 0.f, 0.f);

    #pragma unroll
    for (int s = 0; s < 4; s++) {
        const int r = resos[s];
        const float rm1 = (float)(r - 1);

        float fx = (cx + 1.0f) * 0.5f * rm1;
        float fy = (cy + 1.0f) * 0.5f * rm1;
        fx = fminf(fmaxf(fx, 0.0f), rm1);
        fy = fminf(fmaxf(fy, 0.0f), rm1);

        const float x0f = floorf(fx);
        const float y0f = floorf(fy);
        const float wx = fx - x0f;
        const float wy = fy - y0f;
        const int x0 = (int)x0f;
        const int y0 = (int)y0f;
        const int x1 = min(x0 + 1, r - 1);
        const int y1 = min(y0 + 1, r - 1);

        const float* base = g_tp + offs[s];
        const size_t row0 = (size_t)(p * r + y0) * r;
        const size_t row1 = (size_t)(p * r + y1) * r;

        const float4 v00 = __ldg((const float4*)(base + (row0 + x0) * CDIM) + k);
        const float4 v01 = __ldg((const float4*)(base + (row0 + x1) * CDIM) + k);
        const float4 v10 = __ldg((const float4*)(base + (row1 + x0) * CDIM) + k);
        const float4 v11 = __ldg((const float4*)(base + (row1 + x1) * CDIM) + k);

        const float w00 = (1.0f - wx) * (1.0f - wy);
        const float w01 = wx * (1.0f - wy);
        const float w10 = (1.0f - wx) * wy;
        const float w11 = wx * wy;

        acc.x += v00.x * w00 + v01.x * w01 + v10.x * w10 + v11.x * w11;
        acc.y += v00.y * w00 + v01.y * w01 + v10.y * w10 + v11.y * w11;
        acc.z += v00.z * w00 + v01.z * w01 + v10.z * w10 + v11.z * w11;
        acc.w += v00.w * w00 + v01.w * w01 + v10.w * w10 + v11.w * w11;

        __stcs((float4*)(outrow + s * 216), acc);
    }
}

extern "C" void kernel_launch(void* const* d_in, const int* in_sizes, int n_in,
                              void* d_out, int out_size)
{
    const float* pts = (const float*)d_in[0];
    const int N = in_sizes[0] / 3;
    float* out = (float*)d_out;

    static const int res[4]  = {64, 128, 256, 512};
    static const int offs[4] = {0, 884736, 4423680, 18579456};

    // Lazily-created side stream + events for capture fork/join (created on
    // the first (correctness) call, outside capture; no device allocations).
    static cudaStream_t s_side = nullptr;
    static cudaEvent_t  s_ev_fork = nullptr, s_ev_join = nullptr;
    static bool s_init = false;
    if (!s_init) {
        s_init = true;
        if (cudaStreamCreateWithFlags(&s_side, cudaStreamNonBlocking) != cudaSuccess)
            s_side = nullptr;
        cudaEventCreateWithFlags(&s_ev_fork, cudaEventDisableTiming);
        cudaEventCreateWithFlags(&s_ev_join, cudaEventDisableTiming);
    }
    const bool fork = (s_side != nullptr && s_ev_fork && s_ev_join);
    cudaStream_t sb = fork ? s_side : (cudaStream_t)0;

    if (fork) {
        cudaEventRecord(s_ev_fork, 0);
        cudaStreamWaitEvent(sb, s_ev_fork, 0);
    }

    // Stream B: sort pipeline (hist assumes g_hist==0; scan_k restores it)
    hist_k<<<(N + 255) / 256, 256, 0, sb>>>(pts, N);
    scan_k<<<1, 512, 0, sb>>>();
    scatter_k<<<(N + 255) / 256, 256, 0, sb>>>(pts, N);

    // Stream A (capture stream): transposes
    for (int s = 0; s < 4; s++) {
        const float* g = (const float*)d_in[1 + s];
        const int r2 = res[s] * res[s];
        dim3 grid(r2 / 64, 3);
        transpose_k<<<grid, 288>>>(g, offs[s], r2);
    }

    if (fork) {
        cudaEventRecord(s_ev_join, sb);
        cudaStreamWaitEvent(0, s_ev_join, 0);
    }

    // gather (needs sort + transposes)
    const int total = N * THREADS_PER_PT;
    gather_k<<<(total + 255) / 256, 256>>>(out, N);
}

// round 9
// speedup vs baseline: 1.4491x; 1.1442x over previous
#include <cuda_runtime.h>
#include <cuda_fp16.h>

// Triplane sampling, GB300 (sm_103a).
// Stream A (capture): transpose s3 (fp32->fp16, 339MB) -> [join] -> gather
// Stream B (forked):  hist -> scan -> scatter -> transpose s0,s1,s2
// fp16 channel-major scratch: [scale][plane][texel][72] halves (150 MB).

#define CDIM 72
#define NCHUNK_H 9           // 72 / 8 halves per uint4 chunk
#define THREADS_PER_PT 27    // 3 planes * 9 chunks
#define NBUCKET 4096

__device__ __half g_tph[75202560];     // 150.4 MB fp16 scratch
__device__ float  g_ptss[262144 * 3];  // spatially sorted points
__device__ int    g_perm[262144];      // sorted position -> original index
__device__ int    g_hist[NBUCKET];     // zero-init; scan_k restores zeros
__device__ int    g_base[NBUCKET];

__device__ __forceinline__ unsigned h2_bits(__half2 h) {
    union { __half2 h; unsigned u; } cv;
    cv.h = h;
    return cv.u;
}

// ---------------- sort: bucket key (3D Morton, 4 bits/dim) ----------------
__device__ __forceinline__ int pt_key(const float* __restrict__ pts, int n) {
    int k = 0;
    #pragma unroll
    for (int d = 0; d < 3; d++) {
        float u = fminf(fmaxf(-0.625f * pts[3 * n + d], -1.f), 1.f) * 0.5f + 0.5f;
        int q = min(15, (int)(u * 16.0f));
        #pragma unroll
        for (int b = 0; b < 4; b++)
            k |= ((q >> b) & 1) << (3 * b + d);
    }
    return k;
}

__global__ void hist_k(const float* __restrict__ pts, int N) {
    int n = blockIdx.x * blockDim.x + threadIdx.x;
    if (n < N) atomicAdd(&g_hist[pt_key(pts, n)], 1);
}

__global__ __launch_bounds__(512) void scan_k() {
    __shared__ int sh[512];
    const int t = threadIdx.x;
    int v[8];
    int s = 0;
    #pragma unroll
    for (int i = 0; i < 8; i++) { v[i] = g_hist[t * 8 + i]; s += v[i]; }
    #pragma unroll
    for (int i = 0; i < 8; i++) g_hist[t * 8 + i] = 0;  // restore for next replay
    sh[t] = s;
    __syncthreads();
    for (int off = 1; off < 512; off <<= 1) {
        int x = (t >= off) ? sh[t - off] : 0;
        __syncthreads();
        sh[t] += x;
        __syncthreads();
    }
    int excl = sh[t] - s;
    #pragma unroll
    for (int i = 0; i < 8; i++) { g_base[t * 8 + i] = excl; excl += v[i]; }
}

__global__ void scatter_k(const float* __restrict__ pts, int N) {
    int n = blockIdx.x * blockDim.x + threadIdx.x;
    if (n >= N) return;
    int pos = atomicAdd(&g_base[pt_key(pts, n)], 1);
    g_perm[pos] = n;
    g_ptss[pos * 3 + 0] = pts[n * 3 + 0];
    g_ptss[pos * 3 + 1] = pts[n * 3 + 1];
    g_ptss[pos * 3 + 2] = pts[n * 3 + 2];
}

// ---------------- transpose: [3,72,r2] fp32 -> [3, r2, 72] fp16 ----------------
// One block = one plane x 64 texels x 72 channels. 288 threads.
// Load: LDG.128 (16 threads cover 64 texels per channel row).
// Store: uint4 = 8 halves, block-contiguous.
__global__ __launch_bounds__(288) void transpose_k(
    const float* __restrict__ in, int off, int r2)
{
    __shared__ float tile[64 * 77];
    const int p   = blockIdx.y;
    const int t0  = blockIdx.x * 64;
    const int tid = threadIdx.x;

    const float* src = in + (size_t)p * CDIM * r2 + t0;
    #pragma unroll
    for (int i = 0; i < 4; i++) {
        int idx = i * 288 + tid;          // 0..1151
        int c = idx >> 4;                 // channel 0..71
        int v = idx & 15;                 // float4 index over 64 texels
        float4 d = __ldg((const float4*)(src + (size_t)c * r2) + v);
        float* tp = tile + (4 * v) * 77 + c;
        tp[0 * 77] = d.x;
        tp[1 * 77] = d.y;
        tp[2 * 77] = d.z;
        tp[3 * 77] = d.w;
    }
    __syncthreads();

    uint4* dst = (uint4*)(g_tph + off) + ((size_t)p * r2 + t0) * NCHUNK_H;
    #pragma unroll
    for (int i = 0; i < 2; i++) {
        int lin = i * 288 + tid;          // 0..575
        int x = lin / NCHUNK_H;
        int q = lin - x * NCHUNK_H;
        const float* tp = tile + x * 77 + 8 * q;
        uint4 o;
        o.x = h2_bits(__floats2half2_rn(tp[0], tp[1]));
        o.y = h2_bits(__floats2half2_rn(tp[2], tp[3]));
        o.z = h2_bits(__floats2half2_rn(tp[4], tp[5]));
        o.w = h2_bits(__floats2half2_rn(tp[6], tp[7]));
        dst[lin] = o;
    }
}

// ---------------- gather ----------------
__global__ __launch_bounds__(256) void gather_k(
    float* __restrict__ out, int N)
{
    const int gid = blockIdx.x * blockDim.x + threadIdx.x;
    if (gid >= N * THREADS_PER_PT) return;

    const int n = gid / THREADS_PER_PT;       // sorted position
    const int j = gid - n * THREADS_PER_PT;
    const int p = j / NCHUNK_H;               // plane
    const int k = j - p * NCHUNK_H;           // 8-half chunk

    const float d0 = -0.625f * g_ptss[3 * n + 0];
    const float d1 = -0.625f * g_ptss[3 * n + 1];
    const float d2 = -0.625f * g_ptss[3 * n + 2];

    const float cx = (p == 2) ? d1 : d0;
    const float cy = (p == 0) ? d1 : d2;

    const int resos[4] = {64, 128, 256, 512};
    const int offs[4]  = {0, 884736, 4423680, 18579456};

    const int orig = g_perm[n];
    float* outrow = out + (size_t)orig * 864 + p * CDIM + k * 8;

    float acc[8];
    #pragma unroll
    for (int i = 0; i < 8; i++) acc[i] = 0.0f;

    #pragma unroll
    for (int s = 0; s < 4; s++) {
        const int r = resos[s];
        const float rm1 = (float)(r - 1);

        float fx = (cx + 1.0f) * 0.5f * rm1;
        float fy = (cy + 1.0f) * 0.5f * rm1;
        fx = fminf(fmaxf(fx, 0.0f), rm1);
        fy = fminf(fmaxf(fy, 0.0f), rm1);

        const float x0f = floorf(fx);
        const float y0f = floorf(fy);
        const float wx = fx - x0f;
        const float wy = fy - y0f;
        const int x0 = (int)x0f;
        const int y0 = (int)y0f;
        const int x1 = min(x0 + 1, r - 1);
        const int y1 = min(y0 + 1, r - 1);

        const __half* base = g_tph + offs[s];
        const size_t row0 = (size_t)(p * r + y0) * r;
        const size_t row1 = (size_t)(p * r + y1) * r;

        const uint4 u00 = __ldg((const uint4*)(base + (row0 + x0) * CDIM) + k);
        const uint4 u01 = __ldg((const uint4*)(base + (row0 + x1) * CDIM) + k);
        const uint4 u10 = __ldg((const uint4*)(base + (row1 + x0) * CDIM) + k);
        const uint4 u11 = __ldg((const uint4*)(base + (row1 + x1) * CDIM) + k);

        const float w00 = (1.0f - wx) * (1.0f - wy);
        const float w01 = wx * (1.0f - wy);
        const float w10 = (1.0f - wx) * wy;
        const float w11 = wx * wy;

        #pragma unroll
        for (int h = 0; h < 4; h++) {
            const unsigned a00 = (&u00.x)[h], a01 = (&u01.x)[h];
            const unsigned a10 = (&u10.x)[h], a11 = (&u11.x)[h];
            float2 f00 = __half22float2(*(const __half2*)&a00);
            float2 f01 = __half22float2(*(const __half2*)&a01);
            float2 f10 = __half22float2(*(const __half2*)&a10);
            float2 f11 = __half22float2(*(const __half2*)&a11);
            acc[2*h+0] += f00.x * w00 + f01.x * w01 + f10.x * w10 + f11.x * w11;
            acc[2*h+1] += f00.y * w00 + f01.y * w01 + f10.y * w10 + f11.y * w11;
        }

        __stcs((float4*)(outrow + s * 216),
               make_float4(acc[0], acc[1], acc[2], acc[3]));
        __stcs((float4*)(outrow + s * 216) + 1,
               make_float4(acc[4], acc[5], acc[6], acc[7]));
    }
}

extern "C" void kernel_launch(void* const* d_in, const int* in_sizes, int n_in,
                              void* d_out, int out_size)
{
    const float* pts = (const float*)d_in[0];
    const int N = in_sizes[0] / 3;
    float* out = (float*)d_out;

    static const int res[4]  = {64, 128, 256, 512};
    static const int offs[4] = {0, 884736, 4423680, 18579456};

    static cudaStream_t s_side = nullptr;
    static cudaEvent_t  s_ev_fork = nullptr, s_ev_join = nullptr;
    static bool s_init = false;
    if (!s_init) {
        s_init = true;
        if (cudaStreamCreateWithFlags(&s_side, cudaStreamNonBlocking) != cudaSuccess)
            s_side = nullptr;
        cudaEventCreateWithFlags(&s_ev_fork, cudaEventDisableTiming);
        cudaEventCreateWithFlags(&s_ev_join, cudaEventDisableTiming);
    }
    const bool fork = (s_side != nullptr && s_ev_fork && s_ev_join);
    cudaStream_t sb = fork ? s_side : (cudaStream_t)0;

    if (fork) {
        cudaEventRecord(s_ev_fork, 0);
        cudaStreamWaitEvent(sb, s_ev_fork, 0);
    }

    // Stream A: the big scale-3 transpose (critical path)
    {
        const float* g = (const float*)d_in[4];
        const int r2 = 512 * 512;
        dim3 grid(r2 / 64, 3);
        transpose_k<<<grid, 288>>>(g, offs[3], r2);
    }

    // Stream B: sort pipeline + small transposes (hidden under stream A)
    hist_k<<<(N + 255) / 256, 256, 0, sb>>>(pts, N);
    scan_k<<<1, 512, 0, sb>>>();
    scatter_k<<<(N + 255) / 256, 256, 0, sb>>>(pts, N);
    for (int s = 0; s < 3; s++) {
        const float* g = (const float*)d_in[1 + s];
        const int r2 = res[s] * res[s];
        dim3 grid(r2 / 64, 3);
        transpose_k<<<grid, 288, 0, sb>>>(g, offs[s], r2);
    }

    if (fork) {
        cudaEventRecord(s_ev_join, sb);
        cudaStreamWaitEvent(0, s_ev_join, 0);
    }

    // gather (needs everything)
    const int total = N * THREADS_PER_PT;
    gather_k<<<(total + 255) / 256, 256>>>(out, N);
}